// round 1
// baseline (speedup 1.0000x reference)
#include <cuda_runtime.h>
#include <cuda_bf16.h>
#include <math.h>

// Problem constants (match reference)
#define N_RAYS   131072
#define NS       128     // coarse samples (NUM_STEPS)
#define T_CDF    127     // cdf length = NUM_STEPS-1
#define NW       126     // interior weights used (weights[:,1:-1])
#define UPS      128     // UPSAMPLE_STEPS
#define TT       256     // total samples per ray
#define WPB      8       // warps (rays) per block

__global__ void __launch_bounds__(WPB * 32)
volume_renderer_kernel(const float* __restrict__ rays_o,
                       const float* __restrict__ rays_d,
                       const float* __restrict__ weights,
                       float* __restrict__ out)
{
    const int warp = threadIdx.x >> 5;
    const int lane = threadIdx.x & 31;
    const int ray  = blockIdx.x * WPB + warp;

    // Per-warp scratch: cdf[128] | zv[128] | nz[128] | za[256]  = 640 floats
    __shared__ float sh[WPB][640];
    float* cdf = sh[warp];
    float* zv  = cdf + 128;
    float* nz  = zv  + 128;
    float* za  = nz  + 128;

    // ---- ray params ----
    const float ox = rays_o[ray * 3 + 0];
    const float oy = rays_o[ray * 3 + 1];
    const float oz = rays_o[ray * 3 + 2];
    const float radius = sqrtf(ox * ox + oy * oy + oz * oz);
    const float nears  = radius - 1.0f;           // BOUND = 1
    const float step   = 2.0f / 127.0f;           // (fars-nears)/(NS-1), fars-nears == 2 exactly

    // ---- Phase A: load interior weights, warp-inclusive scan -> cdf ----
    const float* wrow = weights + (size_t)ray * NS;
    float scan[4];
    float carry = 0.0f;
    #pragma unroll
    for (int g = 0; g < 4; g++) {
        int k = g * 32 + lane;                    // 0..127; valid weights k<126
        float v = (k < NW) ? (wrow[1 + k] + 1e-5f) : 0.0f;
        #pragma unroll
        for (int off = 1; off < 32; off <<= 1) {
            float n = __shfl_up_sync(0xffffffffu, v, off);
            if (lane >= off) v += n;
        }
        v += carry;
        scan[g] = v;
        carry = __shfl_sync(0xffffffffu, v, 31);
    }
    const float inv_total = 1.0f / carry;         // carry = sum of 126 (w+1e-5)

    if (lane == 0) cdf[0] = 0.0f;
    #pragma unroll
    for (int g = 0; g < 4; g++) {
        int k = g * 32 + lane;
        if (k < NW) cdf[k + 1] = scan[g] * inv_total;   // cdf[1..126]
    }
    // coarse z grid into shared (needed for exact-merge tie handling)
    #pragma unroll
    for (int g = 0; g < 4; g++) {
        int i = g * 32 + lane;
        zv[i] = nears + step * (float)i;
    }
    __syncwarp();

    // ---- Phase B: stratified inverse-CDF sampling (4 samples/lane) ----
    #pragma unroll
    for (int g = 0; g < 4; g++) {
        int j = g * 32 + lane;
        float u = ((float)j + 0.5f) * (1.0f / 128.0f);  // exact linspace midpoints
        // searchsorted(cdf, u, side='right') on cdf[0..126]
        int lo = 0, hi = T_CDF;
        while (lo < hi) {
            int mid = (lo + hi) >> 1;
            if (cdf[mid] <= u) lo = mid + 1; else hi = mid;
        }
        int below = lo - 1; if (below < 0) below = 0;
        int above = lo;     if (above > T_CDF - 1) above = T_CDF - 1;
        float clo = cdf[below];
        float chi = cdf[above];
        // bins = z_vals_mid[k] = nears + step*(k + 0.5)
        float blo = nears + step * ((float)below + 0.5f);
        float bhi = nears + step * ((float)above + 0.5f);
        float denom = chi - clo;
        if (denom < 1e-5f) denom = 1.0f;
        float t = (u - clo) / denom;
        nz[j] = blo + t * (bhi - blo);
    }
    __syncwarp();

    // ---- Phase C: merge zv (128) and nz (128) into za (256) via ranks ----
    // zv element i final pos = i + |{ nz < zv[i] }|   (strict)
    // nz element j final pos = j + |{ zv <= nz[j] }|  (non-strict)  -> bijection
    #pragma unroll
    for (int g = 0; g < 4; g++) {
        int i = g * 32 + lane;
        {
            float v = zv[i];
            int lo = 0, hi = UPS;
            while (lo < hi) {
                int mid = (lo + hi) >> 1;
                if (nz[mid] < v) lo = mid + 1; else hi = mid;
            }
            za[i + lo] = v;
        }
        {
            float v = nz[i];
            int lo = 0, hi = NS;
            while (lo < hi) {
                int mid = (lo + hi) >> 1;
                if (zv[mid] <= v) lo = mid + 1; else hi = mid;
            }
            za[i + lo] = v;
        }
    }
    __syncwarp();

    // ---- Phase D: coalesced output, 256 points * 3 comps = 768 floats/ray ----
    const float dx = rays_d[ray * 3 + 0];
    const float dy = rays_d[ray * 3 + 1];
    const float dz = rays_d[ray * 3 + 2];
    float* orow = out + (size_t)ray * (TT * 3);
    #pragma unroll
    for (int s = 0; s < 6; s++) {
        int q = s * 32 + lane;       // float4 index 0..191
        int f = q * 4;               // flat float index
        float vals[4];
        #pragma unroll
        for (int e = 0; e < 4; e++) {
            int ff = f + e;
            int p  = ff / 3;
            int c  = ff - p * 3;
            float oc = (c == 0) ? ox : ((c == 1) ? oy : oz);
            float dc = (c == 0) ? dx : ((c == 1) ? dy : dz);
            float v = fmaf(dc, za[p], oc);
            v = fminf(fmaxf(v, -1.0f), 1.0f);
            vals[e] = v;
        }
        float4 r; r.x = vals[0]; r.y = vals[1]; r.z = vals[2]; r.w = vals[3];
        reinterpret_cast<float4*>(orow)[q] = r;
    }
}

extern "C" void kernel_launch(void* const* d_in, const int* in_sizes, int n_in,
                              void* d_out, int out_size)
{
    const float* rays_o  = (const float*)d_in[0];
    const float* rays_d  = (const float*)d_in[1];
    const float* weights = (const float*)d_in[2];
    float* out = (float*)d_out;
    volume_renderer_kernel<<<N_RAYS / WPB, WPB * 32>>>(rays_o, rays_d, weights, out);
}

// round 3
// speedup vs baseline: 1.5788x; 1.5788x over previous
#include <cuda_runtime.h>
#include <cuda_bf16.h>
#include <math.h>

#define WPB  8
#define FULL 0xffffffffu

struct WS {
    float cdf[128];
    float za[256];
    int   buf[256];
};

__global__ void __launch_bounds__(WPB * 32)
volume_renderer_kernel(const float* __restrict__ rays_o,
                       const float* __restrict__ rays_d,
                       const float* __restrict__ weights,
                       float* __restrict__ out)
{
    __shared__ WS sh[WPB];
    const int warp = threadIdx.x >> 5;
    const int lane = threadIdx.x & 31;
    const int ray  = blockIdx.x * WPB + warp;
    WS& S = sh[warp];

    const float ox = rays_o[ray * 3 + 0];
    const float oy = rays_o[ray * 3 + 1];
    const float oz = rays_o[ray * 3 + 2];
    const float radius  = sqrtf(fmaf(ox, ox, fmaf(oy, oy, oz * oz)));
    const float nears   = radius - 1.0f;          // BOUND = 1, fars-nears = 2
    const float step    = 2.0f / 127.0f;
    const float invstep = 63.5f;                  // exact

    // ---- Phase A: weights -> normalized cdf (2-level scan, float4 load) ----
    // lane owns k = 4l..4l+3 ; a_k = (1<=k<=126) ? w[k]+1e-5 : 0
    const float4 w4 = __ldcs(reinterpret_cast<const float4*>(weights + (size_t)ray * 128) + lane);
    float a0 = (lane == 0)  ? 0.0f : w4.x + 1e-5f;
    float a1 = w4.y + 1e-5f;
    float a2 = w4.z + 1e-5f;
    float a3 = (lane == 31) ? 0.0f : w4.w + 1e-5f;
    float q0 = a0, q1 = q0 + a1, q2 = q1 + a2, q3 = q2 + a3;
    float v = q3;
    #pragma unroll
    for (int off = 1; off < 32; off <<= 1) {
        float n = __shfl_up_sync(FULL, v, off);
        if (lane >= off) v += n;
    }
    float excl = __shfl_up_sync(FULL, v, 1);
    if (lane == 0) excl = 0.0f;
    const float total = __shfl_sync(FULL, v, 31);
    const float inv   = 1.0f / total;
    const float c0 = (excl + q0) * inv;
    const float c1 = (excl + q1) * inv;
    const float c2 = (excl + q2) * inv;
    const float c3 = (excl + q3) * inv;
    reinterpret_cast<float4*>(S.cdf)[lane] = make_float4(c0, c1, c2, c3);
    reinterpret_cast<int4*>(S.buf)[lane]   = make_int4(0, 0, 0, 0);
    __syncwarp();

    // ---- Phase B (inverted searchsorted): scatter j_m = ceil(128*cdf[m]-0.5) ----
    {
        const float cs[4] = {c0, c1, c2, c3};
        #pragma unroll
        for (int e = 0; e < 4; e++) {
            int m = 4 * lane + e;
            if (m >= 1 && m <= 126) {
                int jm = (int)ceilf(fmaf(128.0f, cs[e], -0.5f));
                if (jm < 0) jm = 0;
                if (jm <= 127) atomicMax(&S.buf[jm], m);
            }
        }
    }
    __syncwarp();

    // ---- max-scan over buf[0..127] -> below[j] for j = 4l..4l+3 ----
    int4 ar = reinterpret_cast<int4*>(S.buf)[lane];
    int b0 = ar.x;
    int b1 = max(b0, ar.y);
    int b2 = max(b1, ar.z);
    int b3 = max(b2, ar.w);
    int mv = b3;
    #pragma unroll
    for (int off = 1; off < 32; off <<= 1) {
        int n = __shfl_up_sync(FULL, mv, off);
        if (lane >= off) mv = max(mv, n);
    }
    int mexcl = __shfl_up_sync(FULL, mv, 1);
    if (lane == 0) mexcl = 0;
    const int Bs[4] = {max(mexcl, b0), max(mexcl, b1), max(mexcl, b2), max(mexcl, b3)};

    __syncwarp();   // everyone done reading buf; safe to re-init for the merge marks
    reinterpret_cast<int4*>(S.buf)[lane]      = make_int4(0, 0, 0, 0);
    reinterpret_cast<int4*>(S.buf)[lane + 32] = make_int4(0, 0, 0, 0);

    // ---- inverse-CDF sample + O(1) merge rank (all in regs) ----
    float nzv[4];
    int   pos[4];
    #pragma unroll
    for (int e = 0; e < 4; e++) {
        int j = 4 * lane + e;
        float u = ((float)j + 0.5f) * 0.0078125f;   // exact linspace midpoint
        int B = Bs[e];
        int A = min(B + 1, 126);
        float clo = S.cdf[B];
        float chi = S.cdf[A];
        float blo = fmaf(step, (float)B + 0.5f, nears);   // z_vals_mid[B]
        float bhi = fmaf(step, (float)A + 0.5f, nears);
        float denom = chi - clo;
        if (denom < 1e-5f) denom = 1.0f;
        float t  = (u - clo) / denom;
        float nz = fmaf(t, bhi - blo, blo);
        nzv[e] = nz;
        // rank in uniform coarse grid: #{ zv <= nz } = floor((nz-nears)*invstep)+1
        int kj = (int)floorf((nz - nears) * invstep) + 1;
        if (kj < 0)   kj = 0;
        if (kj > 128) kj = 128;
        pos[e] = j + kj;          // strictly increasing in j -> collision-free
    }
    __syncwarp();   // mark zero-init visible
    #pragma unroll
    for (int e = 0; e < 4; e++) {
        S.za[pos[e]]  = nzv[e];
        S.buf[pos[e]] = 1;
    }
    __syncwarp();

    // ---- 256-wide sum-scan of marks: fill free slots with analytic grid ----
    int4 m0 = reinterpret_cast<int4*>(S.buf)[2 * lane];
    int4 m1 = reinterpret_cast<int4*>(S.buf)[2 * lane + 1];
    int s0 = m0.x, s1 = s0 + m0.y, s2 = s1 + m0.z, s3 = s2 + m0.w;
    int s4 = s3 + m1.x, s5 = s4 + m1.y, s6 = s5 + m1.z, s7 = s6 + m1.w;
    int sv = s7;
    #pragma unroll
    for (int off = 1; off < 32; off <<= 1) {
        int n = __shfl_up_sync(FULL, sv, off);
        if (lane >= off) sv += n;
    }
    int sexcl = __shfl_up_sync(FULL, sv, 1);
    if (lane == 0) sexcl = 0;
    {
        const int ss[8] = {s0, s1, s2, s3, s4, s5, s6, s7};
        const int mk[8] = {m0.x, m0.y, m0.z, m0.w, m1.x, m1.y, m1.z, m1.w};
        #pragma unroll
        for (int r = 0; r < 8; r++) {
            if (!mk[r]) {
                int p = 8 * lane + r;
                int i = p - (sexcl + ss[r]);   // mark==0 -> incl == excl count
                S.za[p] = fmaf(step, (float)i, nears);
            }
        }
    }
    __syncwarp();

    // ---- Phase D: lane owns 8 contiguous points -> compile-time (p,c) map ----
    const float dxyz[3] = { rays_d[ray * 3 + 0], rays_d[ray * 3 + 1], rays_d[ray * 3 + 2] };
    const float oxyz[3] = { ox, oy, oz };
    float4 z0 = reinterpret_cast<float4*>(S.za)[2 * lane];
    float4 z1 = reinterpret_cast<float4*>(S.za)[2 * lane + 1];
    const float zr[8] = {z0.x, z0.y, z0.z, z0.w, z1.x, z1.y, z1.z, z1.w};
    float* orow = out + (size_t)ray * 768 + lane * 24;
    #pragma unroll
    for (int e = 0; e < 6; e++) {
        float vv[4];
        #pragma unroll
        for (int r = 0; r < 4; r++) {
            int idx = 4 * e + r;        // 0..23 (lane-local float index)
            int p = idx / 3;            // compile-time after unroll
            int c = idx % 3;
            float t = fmaf(dxyz[c], zr[p], oxyz[c]);
            vv[r] = fminf(fmaxf(t, -1.0f), 1.0f);
        }
        __stcs(reinterpret_cast<float4*>(orow) + e, make_float4(vv[0], vv[1], vv[2], vv[3]));
    }
}

extern "C" void kernel_launch(void* const* d_in, const int* in_sizes, int n_in,
                              void* d_out, int out_size)
{
    const float* rays_o  = (const float*)d_in[0];
    const float* rays_d  = (const float*)d_in[1];
    const float* weights = (const float*)d_in[2];
    float* out = (float*)d_out;
    volume_renderer_kernel<<<131072 / WPB, WPB * 32>>>(rays_o, rays_d, weights, out);
}

// round 6
// speedup vs baseline: 1.7866x; 1.1317x over previous
#include <cuda_runtime.h>
#include <cuda_bf16.h>
#include <math.h>

#define WPB  8
#define FULL 0xffffffffu

struct WS {
    float cdf[128];
    float za[256];
    int   buf[128];
};

__global__ void __launch_bounds__(WPB * 32)
volume_renderer_kernel(const float* __restrict__ rays_o,
                       const float* __restrict__ rays_d,
                       const float* __restrict__ weights,
                       float* __restrict__ out)
{
    __shared__ WS sh[WPB];
    const int warp = threadIdx.x >> 5;
    const int lane = threadIdx.x & 31;
    const int ray  = blockIdx.x * WPB + warp;
    WS& S = sh[warp];

    const float ox = rays_o[ray * 3 + 0];
    const float oy = rays_o[ray * 3 + 1];
    const float oz = rays_o[ray * 3 + 2];
    const float radius  = sqrtf(fmaf(ox, ox, fmaf(oy, oy, oz * oz)));
    const float nears   = radius - 1.0f;          // BOUND = 1, fars - nears = 2
    const float step    = 2.0f / 127.0f;
    const float invstep = 63.5f;

    // ---- Phase A: weights -> normalized cdf (2-level scan, float4 load) ----
    const float4 w4 = __ldcs(reinterpret_cast<const float4*>(weights + (size_t)ray * 128) + lane);
    float a0 = (lane == 0)  ? 0.0f : w4.x + 1e-5f;
    float a1 = w4.y + 1e-5f;
    float a2 = w4.z + 1e-5f;
    float a3 = (lane == 31) ? 0.0f : w4.w + 1e-5f;
    float q0 = a0, q1 = q0 + a1, q2 = q1 + a2, q3 = q2 + a3;
    float v = q3;
    #pragma unroll
    for (int off = 1; off < 32; off <<= 1) {
        float n = __shfl_up_sync(FULL, v, off);
        if (lane >= off) v += n;
    }
    float excl = __shfl_up_sync(FULL, v, 1);
    if (lane == 0) excl = 0.0f;
    const float total = __shfl_sync(FULL, v, 31);
    const float inv   = 1.0f / total;
    const float c0 = (excl + q0) * inv;
    const float c1 = (excl + q1) * inv;
    const float c2 = (excl + q2) * inv;
    const float c3 = (excl + q3) * inv;
    reinterpret_cast<float4*>(S.cdf)[lane] = make_float4(c0, c1, c2, c3);
    reinterpret_cast<int4*>(S.buf)[lane]   = make_int4(0, 0, 0, 0);
    __syncwarp();

    // ---- Phase B: winner-only scatter of j_m = ceil(128*cdf[m]-0.5) (no atomics) ----
    // jm is nondecreasing in m; the winner for a slot is the largest m mapping to it,
    // i.e. any m with jm[m] < jm[m+1]. Unique writer per slot -> plain STS.
    int jm[4];
    {
        const float cs[4] = {c0, c1, c2, c3};
        #pragma unroll
        for (int e = 0; e < 4; e++) {
            int m = 4 * lane + e;
            if (m >= 1 && m <= 126) {
                int t = (int)ceilf(fmaf(128.0f, cs[e], -0.5f));
                jm[e] = (t < 0) ? 0 : t;
            } else {
                jm[e] = 1000;               // sentinel: never stores, always "greater next"
            }
        }
    }
    int jnext0 = __shfl_down_sync(FULL, jm[0], 1);   // next lane's first jm
    if (lane == 31) jnext0 = 1000;
    #pragma unroll
    for (int e = 0; e < 4; e++) {
        int m   = 4 * lane + e;
        int nxt = (e < 3) ? jm[e + 1] : jnext0;
        if (m >= 1 && m <= 126 && jm[e] <= 127 && jm[e] < nxt)
            S.buf[jm[e]] = m;
    }
    __syncwarp();

    // ---- max-scan over buf[0..127] -> below[j] for j = 4l..4l+3 ----
    int4 ar = reinterpret_cast<int4*>(S.buf)[lane];
    int b0 = ar.x;
    int b1 = max(b0, ar.y);
    int b2 = max(b1, ar.z);
    int b3 = max(b2, ar.w);
    int mv = b3;
    #pragma unroll
    for (int off = 1; off < 32; off <<= 1) {
        int n = __shfl_up_sync(FULL, mv, off);
        if (lane >= off) mv = max(mv, n);
    }
    int mexcl = __shfl_up_sync(FULL, mv, 1);
    if (lane == 0) mexcl = 0;
    const int Bs[4] = {max(mexcl, b0), max(mexcl, b1), max(mexcl, b2), max(mexcl, b3)};

    // ---- inverse-CDF sample + O(1) merge rank ----
    float nzv[4];
    int   pos[4];
    #pragma unroll
    for (int e = 0; e < 4; e++) {
        int j = 4 * lane + e;
        float u = ((float)j + 0.5f) * 0.0078125f;
        int B = Bs[e];
        int A = min(B + 1, 126);
        float clo = S.cdf[B];
        float chi = S.cdf[A];
        float blo = fmaf(step, (float)B + 0.5f, nears);
        float bhi = fmaf(step, (float)A + 0.5f, nears);
        float denom = chi - clo;
        if (denom < 1e-5f) denom = 1.0f;
        float t  = (u - clo) / denom;
        float nz = fmaf(t, bhi - blo, blo);
        nzv[e] = nz;
        int kj = (int)floorf((nz - nears) * invstep) + 1;
        if (kj < 0)   kj = 0;
        if (kj > 128) kj = 128;
        pos[e] = j + kj;            // strictly increasing in j -> all distinct
    }
    // scatter new samples into za
    #pragma unroll
    for (int e = 0; e < 4; e++) S.za[pos[e]] = nzv[e];

    // ---- occupied-slot mask: 256 bits via REDUX.OR, folded consume ----
    const int myw    = lane >> 2;          // word holding this lane's 8 slots
    const int mybase = (lane & 3) * 8;     // bit offset of slot 8*lane within word
    int      cnt_before = 0;               // set bits in words < myw
    unsigned myword     = 0;
    #pragma unroll
    for (int w = 0; w < 8; w++) {
        unsigned c = 0;
        #pragma unroll
        for (int e = 0; e < 4; e++)
            c |= (unsigned)((pos[e] >> 5) == w) << (pos[e] & 31);
        unsigned mm = __reduce_or_sync(FULL, c);
        if (w < myw)  cnt_before += __popc(mm);
        if (w == myw) myword = mm;
    }
    __syncwarp();   // za scatter visible to all lanes

    // ---- Phase D: read 8 contiguous za, fill empty slots analytically, store ----
    const float dxyz[3] = { rays_d[ray * 3 + 0], rays_d[ray * 3 + 1], rays_d[ray * 3 + 2] };
    const float oxyz[3] = { ox, oy, oz };
    float4 z0 = reinterpret_cast<float4*>(S.za)[2 * lane];
    float4 z1 = reinterpret_cast<float4*>(S.za)[2 * lane + 1];
    float zr[8] = {z0.x, z0.y, z0.z, z0.w, z1.x, z1.y, z1.z, z1.w};
    #pragma unroll
    for (int r = 0; r < 8; r++) {
        int bit = mybase + r;
        if (!((myword >> bit) & 1u)) {
            int i = 8 * lane + r - (cnt_before + __popc(myword & ((1u << bit) - 1u)));
            zr[r] = fmaf(step, (float)i, nears);
        }
    }
    float* orow = out + (size_t)ray * 768 + lane * 24;
    #pragma unroll
    for (int e = 0; e < 6; e++) {
        float vv[4];
        #pragma unroll
        for (int r = 0; r < 4; r++) {
            int idx = 4 * e + r;
            int p = idx / 3;        // compile-time after unroll
            int c = idx % 3;
            float t = fmaf(dxyz[c], zr[p], oxyz[c]);
            vv[r] = fminf(fmaxf(t, -1.0f), 1.0f);
        }
        __stcs(reinterpret_cast<float4*>(orow) + e, make_float4(vv[0], vv[1], vv[2], vv[3]));
    }
}

extern "C" void kernel_launch(void* const* d_in, const int* in_sizes, int n_in,
                              void* d_out, int out_size)
{
    const float* rays_o  = (const float*)d_in[0];
    const float* rays_d  = (const float*)d_in[1];
    const float* weights = (const float*)d_in[2];
    float* out = (float*)d_out;
    volume_renderer_kernel<<<131072 / WPB, WPB * 32>>>(rays_o, rays_d, weights, out);
}

// round 8
// speedup vs baseline: 1.8159x; 1.0164x over previous
#include <cuda_runtime.h>
#include <cuda_bf16.h>
#include <math.h>

#define WPB  8
#define FULL 0xffffffffu

struct WS {
    float cdf[128];
    float za[256];
    int   buf[128];    // winners m  (for below-index max-scan)
    int   buf2[128];   // winners j+1 (for coarse-rank max-scan)
};

__global__ void __launch_bounds__(WPB * 32)
volume_renderer_kernel(const float* __restrict__ rays_o,
                       const float* __restrict__ rays_d,
                       const float* __restrict__ weights,
                       float* __restrict__ out)
{
    __shared__ WS sh[WPB];
    const int warp = threadIdx.x >> 5;
    const int lane = threadIdx.x & 31;
    const int ray  = blockIdx.x * WPB + warp;
    WS& S = sh[warp];

    const float ox = rays_o[ray * 3 + 0];
    const float oy = rays_o[ray * 3 + 1];
    const float oz = rays_o[ray * 3 + 2];
    const float radius  = sqrtf(fmaf(ox, ox, fmaf(oy, oy, oz * oz)));
    const float nears   = radius - 1.0f;          // BOUND = 1, fars - nears = 2
    const float step    = 2.0f / 127.0f;
    const float invstep = 63.5f;

    // ---- Phase A: weights -> normalized cdf (2-level scan, float4 load) ----
    const float4 w4 = __ldcs(reinterpret_cast<const float4*>(weights + (size_t)ray * 128) + lane);
    float a0 = (lane == 0)  ? 0.0f : w4.x + 1e-5f;
    float a1 = w4.y + 1e-5f;
    float a2 = w4.z + 1e-5f;
    float a3 = (lane == 31) ? 0.0f : w4.w + 1e-5f;
    float q0 = a0, q1 = q0 + a1, q2 = q1 + a2, q3 = q2 + a3;
    float v = q3;
    #pragma unroll
    for (int off = 1; off < 32; off <<= 1) {
        float n = __shfl_up_sync(FULL, v, off);
        if (lane >= off) v += n;
    }
    float excl = __shfl_up_sync(FULL, v, 1);
    if (lane == 0) excl = 0.0f;
    const float total = __shfl_sync(FULL, v, 31);
    const float inv   = __fdividef(1.0f, total);
    const float c0 = (excl + q0) * inv;
    const float c1 = (excl + q1) * inv;
    const float c2 = (excl + q2) * inv;
    const float c3 = (excl + q3) * inv;
    reinterpret_cast<float4*>(S.cdf)[lane] = make_float4(c0, c1, c2, c3);
    reinterpret_cast<int4*>(S.buf)[lane]   = make_int4(0, 0, 0, 0);
    reinterpret_cast<int4*>(S.buf2)[lane]  = make_int4(0, 0, 0, 0);
    __syncwarp();

    // ---- Phase B: winner-only scatter of j_m = ceil(128*cdf[m]-0.5) ----
    // jm nondecreasing in m; winner per slot = largest m mapping to it (jm[m] < jm[m+1]).
    int jm[4];
    {
        const float cs[4] = {c0, c1, c2, c3};
        #pragma unroll
        for (int e = 0; e < 4; e++) {
            int m = 4 * lane + e;
            if (m >= 1 && m <= 126) {
                int t = (int)ceilf(fmaf(128.0f, cs[e], -0.5f));
                jm[e] = (t < 0) ? 0 : t;
            } else {
                jm[e] = 1000;               // sentinel
            }
        }
    }
    int jnext0 = __shfl_down_sync(FULL, jm[0], 1);
    if (lane == 31) jnext0 = 1000;
    #pragma unroll
    for (int e = 0; e < 4; e++) {
        int m   = 4 * lane + e;
        int nxt = (e < 3) ? jm[e + 1] : jnext0;
        if (m >= 1 && m <= 126 && jm[e] <= 127 && jm[e] < nxt)
            S.buf[jm[e]] = m;
    }
    __syncwarp();

    // ---- max-scan over buf[0..127] -> below[j] for j = 4l..4l+3 ----
    int4 ar = reinterpret_cast<int4*>(S.buf)[lane];
    int b0 = ar.x;
    int b1 = max(b0, ar.y);
    int b2 = max(b1, ar.z);
    int b3 = max(b2, ar.w);
    int mv = b3;
    #pragma unroll
    for (int off = 1; off < 32; off <<= 1) {
        int n = __shfl_up_sync(FULL, mv, off);
        if (lane >= off) mv = max(mv, n);
    }
    int mexcl = __shfl_up_sync(FULL, mv, 1);
    if (lane == 0) mexcl = 0;
    const int Bs[4] = {max(mexcl, b0), max(mexcl, b1), max(mexcl, b2), max(mexcl, b3)};

    // ---- inverse-CDF sample + coarse rank kj; scatter nz -> za[j+kj] ----
    int kj[4];
    #pragma unroll
    for (int e = 0; e < 4; e++) {
        int j = 4 * lane + e;
        float u = ((float)j + 0.5f) * 0.0078125f;
        int B = Bs[e];
        int A = min(B + 1, 126);
        float clo = S.cdf[B];
        float chi = S.cdf[A];
        float blo = fmaf(step, (float)B + 0.5f, nears);
        float bhi = fmaf(step, (float)A + 0.5f, nears);
        float denom = chi - clo;
        if (denom < 1e-5f) denom = 1.0f;
        float t  = __fdividef(u - clo, denom);
        float nz = fmaf(t, bhi - blo, blo);
        int k = (int)floorf((nz - nears) * invstep) + 1;   // #{zv <= nz}
        if (k < 0)   k = 0;
        if (k > 128) k = 128;
        kj[e] = k;
        S.za[j + k] = nz;                // j+k strictly increasing -> distinct
    }

    // ---- winner-only scatter of kj -> buf2 (rank table for coarse samples) ----
    // r_i = #{j : kj <= i} = (largest j with kj <= i) + 1; winner j writes j+1 at slot kj.
    int knext0 = __shfl_down_sync(FULL, kj[0], 1);
    if (lane == 31) knext0 = 1000;
    #pragma unroll
    for (int e = 0; e < 4; e++) {
        int j   = 4 * lane + e;
        int nxt = (e < 3) ? kj[e + 1] : knext0;
        if (kj[e] <= 127 && kj[e] < nxt)
            S.buf2[kj[e]] = j + 1;
    }
    __syncwarp();

    // ---- max-scan over buf2 -> r_i ; scatter coarse za[i + r_i] ----
    int4 cr = reinterpret_cast<int4*>(S.buf2)[lane];
    int r0 = cr.x;
    int r1 = max(r0, cr.y);
    int r2 = max(r1, cr.z);
    int r3 = max(r2, cr.w);
    int rv = r3;
    #pragma unroll
    for (int off = 1; off < 32; off <<= 1) {
        int n = __shfl_up_sync(FULL, rv, off);
        if (lane >= off) rv = max(rv, n);
    }
    int rexcl = __shfl_up_sync(FULL, rv, 1);
    if (lane == 0) rexcl = 0;
    {
        const int rr[4] = {max(rexcl, r0), max(rexcl, r1), max(rexcl, r2), max(rexcl, r3)};
        #pragma unroll
        for (int e = 0; e < 4; e++) {
            int i = 4 * lane + e;
            S.za[i + rr[e]] = fmaf(step, (float)i, nears);
        }
    }
    __syncwarp();

    // ---- Phase D: pure load-transform-store (every za slot written exactly once) ----
    const float dxyz[3] = { rays_d[ray * 3 + 0], rays_d[ray * 3 + 1], rays_d[ray * 3 + 2] };
    const float oxyz[3] = { ox, oy, oz };
    float4 z0 = reinterpret_cast<float4*>(S.za)[2 * lane];
    float4 z1 = reinterpret_cast<float4*>(S.za)[2 * lane + 1];
    const float zr[8] = {z0.x, z0.y, z0.z, z0.w, z1.x, z1.y, z1.z, z1.w};
    float* orow = out + (size_t)ray * 768 + lane * 24;
    #pragma unroll
    for (int e = 0; e < 6; e++) {
        float vv[4];
        #pragma unroll
        for (int r = 0; r < 4; r++) {
            int idx = 4 * e + r;
            int p = idx / 3;        // compile-time after unroll
            int c = idx % 3;
            float t = fmaf(dxyz[c], zr[p], oxyz[c]);
            vv[r] = fminf(fmaxf(t, -1.0f), 1.0f);
        }
        __stcs(reinterpret_cast<float4*>(orow) + e, make_float4(vv[0], vv[1], vv[2], vv[3]));
    }
}

extern "C" void kernel_launch(void* const* d_in, const int* in_sizes, int n_in,
                              void* d_out, int out_size)
{
    const float* rays_o  = (const float*)d_in[0];
    const float* rays_d  = (const float*)d_in[1];
    const float* weights = (const float*)d_in[2];
    float* out = (float*)d_out;
    volume_renderer_kernel<<<131072 / WPB, WPB * 32>>>(rays_o, rays_d, weights, out);
}

// round 9
// speedup vs baseline: 1.9120x; 1.0529x over previous
#include <cuda_runtime.h>
#include <cuda_bf16.h>
#include <math.h>

#define WPB  8
#define FULL 0xffffffffu

struct WS {
    float cdf[128];
    float za[256];
    unsigned char bm[128];   // winners m   (below-index max-scan), values 0..126
    unsigned char bj[128];   // winners j+1 (coarse-rank max-scan), values 0..128
};

__global__ void __launch_bounds__(WPB * 32)
volume_renderer_kernel(const float* __restrict__ rays_o,
                       const float* __restrict__ rays_d,
                       const float* __restrict__ weights,
                       float* __restrict__ out)
{
    __shared__ WS sh[WPB];
    const int warp = threadIdx.x >> 5;
    const int lane = threadIdx.x & 31;
    const int ray  = blockIdx.x * WPB + warp;
    WS& S = sh[warp];

    const float ox = rays_o[ray * 3 + 0];
    const float oy = rays_o[ray * 3 + 1];
    const float oz = rays_o[ray * 3 + 2];
    const float radius  = sqrtf(fmaf(ox, ox, fmaf(oy, oy, oz * oz)));
    const float nears   = radius - 1.0f;          // BOUND = 1, fars - nears = 2
    const float step    = 2.0f / 127.0f;
    const float invstep = 63.5f;

    // ---- Phase A: weights -> normalized cdf (2-level scan, float4 load) ----
    const float4 w4 = __ldcs(reinterpret_cast<const float4*>(weights + (size_t)ray * 128) + lane);
    float a0 = (lane == 0)  ? 0.0f : w4.x + 1e-5f;
    float a1 = w4.y + 1e-5f;
    float a2 = w4.z + 1e-5f;
    float a3 = (lane == 31) ? 0.0f : w4.w + 1e-5f;
    float q0 = a0, q1 = q0 + a1, q2 = q1 + a2, q3 = q2 + a3;
    float v = q3;
    #pragma unroll
    for (int off = 1; off < 32; off <<= 1) {
        float n = __shfl_up_sync(FULL, v, off);
        if (lane >= off) v += n;
    }
    float excl = __shfl_up_sync(FULL, v, 1);
    if (lane == 0) excl = 0.0f;
    const float total = __shfl_sync(FULL, v, 31);
    const float inv   = __fdividef(1.0f, total);
    const float c0 = (excl + q0) * inv;
    const float c1 = (excl + q1) * inv;
    const float c2 = (excl + q2) * inv;
    const float c3 = (excl + q3) * inv;
    reinterpret_cast<float4*>(S.cdf)[lane] = make_float4(c0, c1, c2, c3);
    // zero both byte rank-tables: one STS.32 per lane per table
    *reinterpret_cast<int*>(S.bm + 4 * lane) = 0;
    *reinterpret_cast<int*>(S.bj + 4 * lane) = 0;
    __syncwarp();

    // ---- Phase B: winner-only scatter of j_m = ceil(128*cdf[m]-0.5) ----
    // jm nondecreasing in m; winner per slot = largest m mapping to it (jm[m] < jm[m+1]).
    int jm[4];
    {
        const float cs[4] = {c0, c1, c2, c3};
        #pragma unroll
        for (int e = 0; e < 4; e++) {
            int m = 4 * lane + e;
            if (m >= 1 && m <= 126) {
                int t = (int)ceilf(fmaf(128.0f, cs[e], -0.5f));
                jm[e] = (t < 0) ? 0 : t;
            } else {
                jm[e] = 1000;               // sentinel
            }
        }
    }
    int jnext0 = __shfl_down_sync(FULL, jm[0], 1);
    if (lane == 31) jnext0 = 1000;
    #pragma unroll
    for (int e = 0; e < 4; e++) {
        int m   = 4 * lane + e;
        int nxt = (e < 3) ? jm[e + 1] : jnext0;
        if (m >= 1 && m <= 126 && jm[e] <= 127 && jm[e] < nxt)
            S.bm[jm[e]] = (unsigned char)m;
    }
    __syncwarp();

    // ---- max-scan over bm[0..127] -> below[j] for j = 4l..4l+3 ----
    // one LDS.32 per lane carries its 4 table bytes
    const unsigned mw = *reinterpret_cast<const int*>(S.bm + 4 * lane);
    int b0 = (int)(mw & 255u);
    int b1 = max(b0, (int)((mw >> 8)  & 255u));
    int b2 = max(b1, (int)((mw >> 16) & 255u));
    int b3 = max(b2, (int)(mw >> 24));
    int mv = b3;
    #pragma unroll
    for (int off = 1; off < 32; off <<= 1) {
        int n = __shfl_up_sync(FULL, mv, off);
        if (lane >= off) mv = max(mv, n);
    }
    int mexcl = __shfl_up_sync(FULL, mv, 1);
    if (lane == 0) mexcl = 0;
    const int Bs[4] = {max(mexcl, b0), max(mexcl, b1), max(mexcl, b2), max(mexcl, b3)};

    // ---- inverse-CDF sample + coarse rank kj; scatter nz -> za[j+kj] ----
    int kj[4];
    #pragma unroll
    for (int e = 0; e < 4; e++) {
        int j = 4 * lane + e;
        float u = ((float)j + 0.5f) * 0.0078125f;
        int B = Bs[e];
        int A = min(B + 1, 126);
        float clo = S.cdf[B];
        float chi = S.cdf[A];
        float blo = fmaf(step, (float)B + 0.5f, nears);
        float bhi = fmaf(step, (float)A + 0.5f, nears);
        float denom = chi - clo;
        if (denom < 1e-5f) denom = 1.0f;
        float t  = __fdividef(u - clo, denom);
        float nz = fmaf(t, bhi - blo, blo);
        int k = (int)floorf((nz - nears) * invstep) + 1;   // #{zv <= nz}
        if (k < 0)   k = 0;
        if (k > 128) k = 128;
        kj[e] = k;
        S.za[j + k] = nz;                // j+k strictly increasing -> distinct
    }

    // ---- winner-only scatter of kj -> bj (rank table for coarse samples) ----
    // r_i = #{j : kj <= i} = (largest j with kj <= i) + 1; winner j writes j+1 at slot kj.
    int knext0 = __shfl_down_sync(FULL, kj[0], 1);
    if (lane == 31) knext0 = 1000;
    #pragma unroll
    for (int e = 0; e < 4; e++) {
        int j   = 4 * lane + e;
        int nxt = (e < 3) ? kj[e + 1] : knext0;
        if (kj[e] <= 127 && kj[e] < nxt)
            S.bj[kj[e]] = (unsigned char)(j + 1);
    }
    __syncwarp();

    // ---- max-scan over bj -> r_i ; scatter coarse za[i + r_i] ----
    const unsigned jw = *reinterpret_cast<const int*>(S.bj + 4 * lane);
    int r0 = (int)(jw & 255u);
    int r1 = max(r0, (int)((jw >> 8)  & 255u));
    int r2 = max(r1, (int)((jw >> 16) & 255u));
    int r3 = max(r2, (int)(jw >> 24));
    int rv = r3;
    #pragma unroll
    for (int off = 1; off < 32; off <<= 1) {
        int n = __shfl_up_sync(FULL, rv, off);
        if (lane >= off) rv = max(rv, n);
    }
    int rexcl = __shfl_up_sync(FULL, rv, 1);
    if (lane == 0) rexcl = 0;
    {
        const int rr[4] = {max(rexcl, r0), max(rexcl, r1), max(rexcl, r2), max(rexcl, r3)};
        #pragma unroll
        for (int e = 0; e < 4; e++) {
            int i = 4 * lane + e;
            S.za[i + rr[e]] = fmaf(step, (float)i, nears);
        }
    }
    __syncwarp();

    // ---- Phase D: pure load-transform-store (every za slot written exactly once) ----
    const float dxyz[3] = { rays_d[ray * 3 + 0], rays_d[ray * 3 + 1], rays_d[ray * 3 + 2] };
    const float oxyz[3] = { ox, oy, oz };
    float4 z0 = reinterpret_cast<float4*>(S.za)[2 * lane];
    float4 z1 = reinterpret_cast<float4*>(S.za)[2 * lane + 1];
    const float zr[8] = {z0.x, z0.y, z0.z, z0.w, z1.x, z1.y, z1.z, z1.w};
    float* orow = out + (size_t)ray * 768 + lane * 24;
    #pragma unroll
    for (int e = 0; e < 6; e++) {
        float vv[4];
        #pragma unroll
        for (int r = 0; r < 4; r++) {
            int idx = 4 * e + r;
            int p = idx / 3;        // compile-time after unroll
            int c = idx % 3;
            float t = fmaf(dxyz[c], zr[p], oxyz[c]);
            vv[r] = fminf(fmaxf(t, -1.0f), 1.0f);
        }
        __stcs(reinterpret_cast<float4*>(orow) + e, make_float4(vv[0], vv[1], vv[2], vv[3]));
    }
}

extern "C" void kernel_launch(void* const* d_in, const int* in_sizes, int n_in,
                              void* d_out, int out_size)
{
    const float* rays_o  = (const float*)d_in[0];
    const float* rays_d  = (const float*)d_in[1];
    const float* weights = (const float*)d_in[2];
    float* out = (float*)d_out;
    volume_renderer_kernel<<<131072 / WPB, WPB * 32>>>(rays_o, rays_d, weights, out);
}

// round 10
// speedup vs baseline: 1.9461x; 1.0179x over previous
#include <cuda_runtime.h>
#include <cuda_bf16.h>
#include <math.h>

#define WPB  8
#define FULL 0xffffffffu

// pad-swizzle for za: 4-word skew per 32-word group -> conflict-free
// float4 reads at 32B/lane stride; bijective so scatters are unaffected.
#define ZIDX(p) ((p) + 4 * ((p) >> 5))

struct WS {
    float cdf[128];
    float za[288];           // 256 live slots under ZIDX (max index 283)
    unsigned char bm[128];   // winners m   (below-index max-scan), values 0..126
    unsigned char bj[128];   // winners j+1 (coarse-rank max-scan), values 0..128
};

__global__ void __launch_bounds__(WPB * 32)
volume_renderer_kernel(const float* __restrict__ rays_o,
                       const float* __restrict__ rays_d,
                       const float* __restrict__ weights,
                       float* __restrict__ out)
{
    __shared__ WS sh[WPB];
    const int warp = threadIdx.x >> 5;
    const int lane = threadIdx.x & 31;
    const int ray  = blockIdx.x * WPB + warp;
    WS& S = sh[warp];

    const float ox = rays_o[ray * 3 + 0];
    const float oy = rays_o[ray * 3 + 1];
    const float oz = rays_o[ray * 3 + 2];
    const float radius  = sqrtf(fmaf(ox, ox, fmaf(oy, oy, oz * oz)));
    const float nears   = radius - 1.0f;          // BOUND = 1, fars - nears = 2
    const float step    = 2.0f / 127.0f;
    const float invstep = 63.5f;

    // ---- Phase A: weights -> normalized cdf (2-level scan, float4 load) ----
    const float4 w4 = __ldcs(reinterpret_cast<const float4*>(weights + (size_t)ray * 128) + lane);
    float a0 = (lane == 0)  ? 0.0f : w4.x + 1e-5f;
    float a1 = w4.y + 1e-5f;
    float a2 = w4.z + 1e-5f;
    float a3 = (lane == 31) ? 0.0f : w4.w + 1e-5f;
    float q0 = a0, q1 = q0 + a1, q2 = q1 + a2, q3 = q2 + a3;
    float v = q3;
    #pragma unroll
    for (int off = 1; off < 32; off <<= 1) {
        float n = __shfl_up_sync(FULL, v, off);
        if (lane >= off) v += n;
    }
    float excl = __shfl_up_sync(FULL, v, 1);
    if (lane == 0) excl = 0.0f;
    const float total = __shfl_sync(FULL, v, 31);
    const float inv   = __fdividef(1.0f, total);
    const float c0 = (excl + q0) * inv;
    const float c1 = (excl + q1) * inv;
    const float c2 = (excl + q2) * inv;
    const float c3 = (excl + q3) * inv;
    reinterpret_cast<float4*>(S.cdf)[lane] = make_float4(c0, c1, c2, c3);
    // zero both byte rank-tables: one STS.32 per lane per table
    *reinterpret_cast<int*>(S.bm + 4 * lane) = 0;
    *reinterpret_cast<int*>(S.bj + 4 * lane) = 0;
    __syncwarp();

    // ---- Phase B: winner-only scatter of j_m = ceil(128*cdf[m]-0.5) ----
    // jm nondecreasing in m; winner per slot = largest m mapping to it (jm[m] < jm[m+1]).
    int jm[4];
    {
        const float cs[4] = {c0, c1, c2, c3};
        #pragma unroll
        for (int e = 0; e < 4; e++) {
            int m = 4 * lane + e;
            if (m >= 1 && m <= 126) {
                int t = (int)ceilf(fmaf(128.0f, cs[e], -0.5f));
                jm[e] = (t < 0) ? 0 : t;
            } else {
                jm[e] = 1000;               // sentinel
            }
        }
    }
    int jnext0 = __shfl_down_sync(FULL, jm[0], 1);
    if (lane == 31) jnext0 = 1000;
    #pragma unroll
    for (int e = 0; e < 4; e++) {
        int m   = 4 * lane + e;
        int nxt = (e < 3) ? jm[e + 1] : jnext0;
        if (m >= 1 && m <= 126 && jm[e] <= 127 && jm[e] < nxt)
            S.bm[jm[e]] = (unsigned char)m;
    }
    __syncwarp();

    // ---- max-scan over bm[0..127] -> below[j] for j = 4l..4l+3 ----
    const unsigned mw = *reinterpret_cast<const int*>(S.bm + 4 * lane);
    int b0 = (int)(mw & 255u);
    int b1 = max(b0, (int)((mw >> 8)  & 255u));
    int b2 = max(b1, (int)((mw >> 16) & 255u));
    int b3 = max(b2, (int)(mw >> 24));
    int mv = b3;
    #pragma unroll
    for (int off = 1; off < 32; off <<= 1) {
        int n = __shfl_up_sync(FULL, mv, off);
        if (lane >= off) mv = max(mv, n);
    }
    int mexcl = __shfl_up_sync(FULL, mv, 1);
    if (lane == 0) mexcl = 0;
    const int Bs[4] = {max(mexcl, b0), max(mexcl, b1), max(mexcl, b2), max(mexcl, b3)};

    // ---- inverse-CDF sample + coarse rank kj; scatter nz -> za[j+kj] ----
    int kj[4];
    #pragma unroll
    for (int e = 0; e < 4; e++) {
        int j = 4 * lane + e;
        float u = ((float)j + 0.5f) * 0.0078125f;
        int B = Bs[e];
        int A = min(B + 1, 126);
        float clo = S.cdf[B];
        float chi = S.cdf[A];
        float blo = fmaf(step, (float)B + 0.5f, nears);
        float bhi = fmaf(step, (float)A + 0.5f, nears);
        float denom = chi - clo;
        if (denom < 1e-5f) denom = 1.0f;
        float t  = __fdividef(u - clo, denom);
        float nz = fmaf(t, bhi - blo, blo);
        int k = (int)floorf((nz - nears) * invstep) + 1;   // #{zv <= nz}
        if (k < 0)   k = 0;
        if (k > 128) k = 128;
        kj[e] = k;
        S.za[ZIDX(j + k)] = nz;          // j+k strictly increasing -> distinct
    }

    // ---- winner-only scatter of kj -> bj (rank table for coarse samples) ----
    // r_i = #{j : kj <= i} = (largest j with kj <= i) + 1; winner j writes j+1 at slot kj.
    int knext0 = __shfl_down_sync(FULL, kj[0], 1);
    if (lane == 31) knext0 = 1000;
    #pragma unroll
    for (int e = 0; e < 4; e++) {
        int j   = 4 * lane + e;
        int nxt = (e < 3) ? kj[e + 1] : knext0;
        if (kj[e] <= 127 && kj[e] < nxt)
            S.bj[kj[e]] = (unsigned char)(j + 1);
    }
    __syncwarp();

    // ---- max-scan over bj -> r_i ; scatter coarse za[i + r_i] ----
    const unsigned jw = *reinterpret_cast<const int*>(S.bj + 4 * lane);
    int r0 = (int)(jw & 255u);
    int r1 = max(r0, (int)((jw >> 8)  & 255u));
    int r2 = max(r1, (int)((jw >> 16) & 255u));
    int r3 = max(r2, (int)(jw >> 24));
    int rv = r3;
    #pragma unroll
    for (int off = 1; off < 32; off <<= 1) {
        int n = __shfl_up_sync(FULL, rv, off);
        if (lane >= off) rv = max(rv, n);
    }
    int rexcl = __shfl_up_sync(FULL, rv, 1);
    if (lane == 0) rexcl = 0;
    {
        const int rr[4] = {max(rexcl, r0), max(rexcl, r1), max(rexcl, r2), max(rexcl, r3)};
        #pragma unroll
        for (int e = 0; e < 4; e++) {
            int i = 4 * lane + e;
            S.za[ZIDX(i + rr[e])] = fmaf(step, (float)i, nears);
        }
    }
    __syncwarp();

    // ---- Phase D: pure load-transform-store (conflict-free swizzled za reads) ----
    const float dxyz[3] = { rays_d[ray * 3 + 0], rays_d[ray * 3 + 1], rays_d[ray * 3 + 2] };
    const float oxyz[3] = { ox, oy, oz };
    const int w0 = ZIDX(8 * lane);       // 8l..8l+7 stay in one 32-group: contiguous words
    float4 z0 = *reinterpret_cast<float4*>(&S.za[w0]);
    float4 z1 = *reinterpret_cast<float4*>(&S.za[w0 + 4]);
    const float zr[8] = {z0.x, z0.y, z0.z, z0.w, z1.x, z1.y, z1.z, z1.w};
    float* orow = out + (size_t)ray * 768 + lane * 24;
    #pragma unroll
    for (int e = 0; e < 6; e++) {
        float vv[4];
        #pragma unroll
        for (int r = 0; r < 4; r++) {
            int idx = 4 * e + r;
            int p = idx / 3;        // compile-time after unroll
            int c = idx % 3;
            float t = fmaf(dxyz[c], zr[p], oxyz[c]);
            vv[r] = fminf(fmaxf(t, -1.0f), 1.0f);
        }
        __stcs(reinterpret_cast<float4*>(orow) + e, make_float4(vv[0], vv[1], vv[2], vv[3]));
    }
}

extern "C" void kernel_launch(void* const* d_in, const int* in_sizes, int n_in,
                              void* d_out, int out_size)
{
    const float* rays_o  = (const float*)d_in[0];
    const float* rays_d  = (const float*)d_in[1];
    const float* weights = (const float*)d_in[2];
    float* out = (float*)d_out;
    volume_renderer_kernel<<<131072 / WPB, WPB * 32>>>(rays_o, rays_d, weights, out);
}